// round 13
// baseline (speedup 1.0000x reference)
#include <cuda_runtime.h>
#include <math.h>
#include <stdint.h>

#define MARGIN            0.3f
#define CLST_SCALE        0.8f
#define SEP_SCALE         0.08f
#define DIV_SCALE         0.01f
#define CONTRASTIVE_SCALE 0.1f

#define MAXC 1024
#define MAXD 1024
#define MAXR 32
#define TPB  128
#define SPN_ROWS 10
#define SPN_D4   64

struct Scratch {
    float cls_n[MAXC];
    float cls_sum[MAXC];
    float sep_sum[MAXC];
    float svec[MAXD];
    float div_sum;
    float ndv;
    float diag;
    unsigned int counter;
};
__device__ Scratch g;

__device__ __forceinline__ float inff() { return __int_as_float(0x7f800000); }

// ===========================================================================
// Kernel A: pure streaming min pass (the 65.5 MB read). Nothing else.
// ===========================================================================
__global__ void __launch_bounds__(TPB, 10)
k_min(const float* __restrict__ sims,
      const int*   __restrict__ labels,
      const int*   __restrict__ pidx,
      int B, int C, int P, int NMIN, int fast_ok) {
    const int tid  = threadIdx.x;
    const int warp = tid >> 5, lane = tid & 31;
    const int nwarp = TPB >> 5;
    const int CP = C * P;
    const int gw = (int)blockIdx.x * nwarp + warp;
    const int stride = NMIN * nwarp;

    // fast path requires every class count >= P (cheap once-per-block check)
    int okf = 1;
    for (int c = tid; c < C; c += TPB)
        okf &= ((pidx[2 * c + 1] - pidx[2 * c]) >= P);
    okf = __syncthreads_and(okf) & fast_ok;

    if (okf) {
        const int n4 = CP >> 2;
        const float NI = -inff();

        // prefetch this warp's labels (<= 4 rows/warp) before streaming
        int lbls[4];
        #pragma unroll
        for (int r = 0; r < 4; r++) {
            int b = gw + r * stride;
            lbls[r] = (b < B) ? labels[b] : 0;
        }

        int r = 0;
        for (int b = gw; b < B; b += stride, r++) {
            const int lbl = (r < 4) ? lbls[r] : labels[b];
            const float4* s4 = (const float4*)(sims + (size_t)b * CP);

            float4 x[8];
            #pragma unroll
            for (int k = 0; k < 8; k++) {
                int vi = lane + 32 * k;
                x[k] = make_float4(NI, NI, NI, NI);
                if (vi < n4) x[k] = s4[vi];
            }

            const int lo = lbl * P, hi = lo + P;
            const int viL = lo >> 2, viH = (hi - 1) >> 2;
            float oth = NI;
            #pragma unroll
            for (int k = 0; k < 8; k++) {
                int vi = lane + 32 * k;
                float m4 = fmaxf(fmaxf(x[k].x, x[k].y), fmaxf(x[k].z, x[k].w));
                if (vi < viL || vi > viH) oth = fmaxf(oth, m4);
            }

            float own = NI;
            const int bidx = 4 * viL + lane;
            if (lane < 16 && bidx < CP) {
                float bv = sims[(size_t)b * CP + bidx];
                if (bidx >= lo && bidx < hi) own = bv;
                else if (bidx <= 4 * viH + 3) oth = fmaxf(oth, bv);
            }

            #pragma unroll
            for (int o = 16; o; o >>= 1) {
                own = fmaxf(own, __shfl_xor_sync(0xFFFFFFFFu, own, o));
                oth = fmaxf(oth, __shfl_xor_sync(0xFFFFFFFFu, oth, o));
            }
            if (lane == 0) {
                float ownd = 1.0f - own;
                float sep  = fmaxf(MARGIN - (1.0f - oth), 0.0f);
                atomicAdd(&g.cls_n[lbl],   1.0f);
                atomicAdd(&g.cls_sum[lbl], ownd);
                atomicAdd(&g.sep_sum[lbl], sep);
            }
        }
    } else {
        for (int b = gw; b < B; b += stride) {
            const float* src = sims + (size_t)b * CP;
            const int lbl = labels[b];
            float ownmax = -inff(), othermax = -inff();
            for (int c = lane; c < C; c += 32) {
                int cnt = pidx[2 * c + 1] - pidx[2 * c];
                if (cnt > P) cnt = P;
                float m = -inff();
                const float* pr = src + c * P;
                for (int p = 0; p < cnt; p++) m = fmaxf(m, pr[p]);
                if (c == lbl) ownmax = m;
                else          othermax = fmaxf(othermax, m);
            }
            #pragma unroll
            for (int o = 16; o; o >>= 1) {
                ownmax   = fmaxf(ownmax,   __shfl_xor_sync(0xFFFFFFFFu, ownmax,   o));
                othermax = fmaxf(othermax, __shfl_xor_sync(0xFFFFFFFFu, othermax, o));
            }
            if (lane == 0) {
                float own   = 1.0f - ownmax;
                float other = 1.0f - othermax;
                float sep   = fmaxf(MARGIN - other, 0.0f);
                atomicAdd(&g.cls_n[lbl],   1.0f);
                atomicAdd(&g.cls_sum[lbl], own);
                atomicAdd(&g.sep_sum[lbl], sep);
            }
        }
    }
}

// ===========================================================================
// Kernel B: proto blocks (grid = C) + last-block lean finalize.
// Runs after kernel A (stream order), so cls sums are complete.
// ===========================================================================
__global__ void __launch_bounds__(TPB, 10)
k_proto_final(const float* __restrict__ protos,
              const int*   __restrict__ pidx,
              const unsigned char* __restrict__ mask,
              float* __restrict__ out,
              int C, int T, int D) {
    const int tid  = threadIdx.x;
    const int warp = tid >> 5, lane = tid & 31;
    const int nwarp = TPB >> 5;

    __shared__ float4 spn[SPN_ROWS * SPN_D4];
    __shared__ float s_inv[MAXR];
    __shared__ float s_rn2[MAXR];
    __shared__ int   s_rvalid[MAXR];
    __shared__ float s_pair;

    // mask dtype detection: uint8 all-true reads as 0x01010101 ints.
    int bad = 0;
    {
        const int* mi = (const int*)mask;
        const int n = T >> 2;
        for (int i = tid; i < n; i += TPB) {
            int v = mi[i];
            bad |= (v != 0 && v != 1);
        }
    }
    const int byte_mode = __syncthreads_or(bad);

    const int c = blockIdx.x;
    int rs = pidx[2 * c];
    int re = (c + 1 < C) ? pidx[2 * (c + 1)] : T;
    if (re > T) re = T;
    if (rs < 0) rs = 0;
    int nr = re - rs;
    if (nr > MAXR) nr = MAXR;
    if (nr < 0) nr = 0;

    if (tid == 0) s_pair = 0.f;
    const bool d4ok = ((D & 3) == 0);
    const int  D4   = D >> 2;
    const float4* p4 = (const float4*)protos;
    const bool smok = d4ok && (nr <= SPN_ROWS) && (D4 <= SPN_D4);

    if (smok) {
        const int nv = nr * D4;
        for (int i = tid; i < nv; i += TPB) {
            int r = i / D4, d = i % D4;
            spn[r * SPN_D4 + d] = p4[(size_t)(rs + r) * D4 + d];
        }
        __syncthreads();

        for (int r = warp; r < nr; r += nwarp) {
            float ss = 0.f;
            for (int d = lane; d < D4; d += 32) {
                float4 x = spn[r * SPN_D4 + d];
                ss += x.x * x.x + x.y * x.y + x.z * x.z + x.w * x.w;
            }
            #pragma unroll
            for (int o = 16; o; o >>= 1) ss += __shfl_xor_sync(0xFFFFFFFFu, ss, o);
            float inv = 1.0f / fmaxf(sqrtf(ss), 1e-12f);
            if (lane == 0) {
                s_inv[r] = inv;
                s_rn2[r] = ss * inv * inv;
                int t = rs + r;
                int v = byte_mode ? (int)mask[t] : ((const int*)mask)[t];
                s_rvalid[r] = (v != 0);
            }
        }
        __syncthreads();

        for (int d = tid; d < D4; d += TPB) {
            float4 acc = make_float4(0.f, 0.f, 0.f, 0.f);
            for (int r = 0; r < nr; r++) {
                if (s_rvalid[r]) {
                    float4 x = spn[r * SPN_D4 + d];
                    float iv = s_inv[r];
                    acc.x += x.x * iv; acc.y += x.y * iv;
                    acc.z += x.z * iv; acc.w += x.w * iv;
                }
            }
            atomicAdd(&g.svec[4 * d + 0], acc.x);
            atomicAdd(&g.svec[4 * d + 1], acc.y);
            atomicAdd(&g.svec[4 * d + 2], acc.z);
            atomicAdd(&g.svec[4 * d + 3], acc.w);
        }
        if (tid == 0) {
            float ds = 0.f;
            for (int r = 0; r < nr; r++) if (s_rvalid[r]) ds += s_rn2[r];
            atomicAdd(&g.diag, ds);
        }

        const int npr = nr * (nr - 1) / 2;
        float local = 0.f;
        for (int k = warp; k < npr; k += nwarp) {
            int i = 0, rem = k;
            while (rem >= nr - 1 - i) { rem -= nr - 1 - i; i++; }
            int j = i + 1 + rem;
            float dot = 0.f;
            for (int d = lane; d < D4; d += 32) {
                float4 a = spn[i * SPN_D4 + d], b = spn[j * SPN_D4 + d];
                dot += a.x * b.x + a.y * b.y + a.z * b.z + a.w * b.w;
            }
            #pragma unroll
            for (int o = 16; o; o >>= 1) dot += __shfl_xor_sync(0xFFFFFFFFu, dot, o);
            if (lane == 0)
                local += 2.0f * fmaxf(dot * s_inv[i] * s_inv[j] - 0.5f, 0.f);
        }
        if (lane == 0 && local != 0.f) atomicAdd(&s_pair, local);
        __syncthreads();
    } else {
        for (int r = warp; r < nr; r += nwarp) {
            float ss = 0.f;
            const float* src = protos + (size_t)(rs + r) * D;
            for (int d = lane; d < D; d += 32) { float v = src[d]; ss += v * v; }
            #pragma unroll
            for (int o = 16; o; o >>= 1) ss += __shfl_xor_sync(0xFFFFFFFFu, ss, o);
            float inv = 1.0f / fmaxf(sqrtf(ss), 1e-12f);
            if (lane == 0) {
                s_inv[r] = inv;
                s_rn2[r] = ss * inv * inv;
                int t = rs + r;
                int v = byte_mode ? (int)mask[t] : ((const int*)mask)[t];
                s_rvalid[r] = (v != 0);
            }
        }
        __syncthreads();

        for (int d = tid; d < D; d += TPB) {
            float s = 0.f;
            for (int r = 0; r < nr; r++)
                if (s_rvalid[r])
                    s += protos[(size_t)(rs + r) * D + d] * s_inv[r];
            atomicAdd(&g.svec[d], s);
        }
        if (tid == 0) {
            float ds = 0.f;
            for (int r = 0; r < nr; r++) if (s_rvalid[r]) ds += s_rn2[r];
            atomicAdd(&g.diag, ds);
        }

        const int npr = nr * (nr - 1) / 2;
        float local = 0.f;
        for (int k = warp; k < npr; k += nwarp) {
            int i = 0, rem = k;
            while (rem >= nr - 1 - i) { rem -= nr - 1 - i; i++; }
            int j = i + 1 + rem;
            const float* ri = protos + (size_t)(rs + i) * D;
            const float* rj = protos + (size_t)(rs + j) * D;
            float dot = 0.f;
            for (int d = lane; d < D; d += 32) dot += ri[d] * rj[d];
            #pragma unroll
            for (int o = 16; o; o >>= 1) dot += __shfl_xor_sync(0xFFFFFFFFu, dot, o);
            if (lane == 0)
                local += 2.0f * fmaxf(dot * s_inv[i] * s_inv[j] - 0.5f, 0.f);
        }
        if (lane == 0 && local != 0.f) atomicAdd(&s_pair, local);
        __syncthreads();
    }

    if (tid == 0) {
        int cnt = pidx[2 * c + 1] - pidx[2 * c];
        if (cnt > 1) {
            float npf = (float)cnt * (float)(cnt - 1);
            atomicAdd(&g.div_sum, s_pair / fmaxf(npf, 1.0f));
            atomicAdd(&g.ndv, 1.0f);
        }
    }

    // ---- last proto block finalizes with one lean warp --------------------
    __threadfence();
    __shared__ unsigned int s_ord;
    if (tid == 0) s_ord = atomicAdd(&g.counter, 1u);
    __syncthreads();
    if (s_ord != (unsigned)(C - 1)) return;
    if (warp != 0) return;
    __threadfence();

    float ca = 0.f, sa = 0.f, nv = 0.f;
    for (int cc = lane; cc < C; cc += 32) {
        float n = g.cls_n[cc];
        if (n > 0.f) {
            nv += 1.f;
            float nm = fmaxf(n, 1.f);
            ca += (1.0f / sqrtf(n + 1e-6f)) * (g.cls_sum[cc] / nm);
            sa += g.sep_sum[cc] / nm;
        }
    }
    float sn = 0.f;
    for (int d = lane; d < D; d += 32) { float v = g.svec[d]; sn += v * v; }
    float vc = 0.f;
    for (int t = lane; t < T; t += 32) {
        int v = byte_mode ? (int)mask[t] : ((const int*)mask)[t];
        vc += (v != 0) ? 1.f : 0.f;
    }

    #pragma unroll
    for (int o = 16; o; o >>= 1) {
        ca += __shfl_xor_sync(0xFFFFFFFFu, ca, o);
        sa += __shfl_xor_sync(0xFFFFFFFFu, sa, o);
        nv += __shfl_xor_sync(0xFFFFFFFFu, nv, o);
        sn += __shfl_xor_sync(0xFFFFFFFFu, sn, o);
        vc += __shfl_xor_sync(0xFFFFFFFFu, vc, o);
    }

    if (lane == 0) {
        float nvalid  = fmaxf(nv, 1.f);
        float cluster = ca / nvalid * CLST_SCALE;
        float sep     = sa / nvalid * SEP_SCALE;
        float divl    = g.div_sum / fmaxf(g.ndv, 1.f) * DIV_SCALE;
        float nvp     = fmaxf(vc * vc - vc, 1.f);
        float contr   = (sn - g.diag) / nvp * CONTRASTIVE_SCALE;
        out[0] = cluster;
        out[1] = sep;
        out[2] = divl;
        out[3] = contr;
        out[4] = cluster + sep + divl + contr;
    }
}

extern "C" void kernel_launch(void* const* d_in, const int* in_sizes, int n_in,
                              void* d_out, int out_size) {
    const float* sims   = (const float*)d_in[0];
    const int*   labels = (const int*)  d_in[1];
    const float* protos = (const float*)d_in[2];
    const int*   pidx   = (const int*)  d_in[3];
    const unsigned char* mask = (const unsigned char*)d_in[4];

    const int B = in_sizes[1];
    const int C = in_sizes[3] / 2;
    const int T = in_sizes[4];
    const int D = in_sizes[2] / T;
    const int P = in_sizes[0] / (B * C);
    float* out = (float*)d_out;

    void* gp = nullptr;
    cudaGetSymbolAddress(&gp, g);
    cudaMemsetAsync(gp, 0, sizeof(Scratch), 0);

    const int CP = C * P;
    const int fast_ok = (((CP & 3) == 0) && (CP <= 1024) && (P <= 13)) ? 1 : 0;

    const int NMIN = 2048;   // 8192 warps -> exactly 2 rows/warp at B=16384
    k_min<<<NMIN, TPB>>>(sims, labels, pidx, B, C, P, NMIN, fast_ok);
    k_proto_final<<<C, TPB>>>(protos, pidx, mask, out, C, T, D);
}

// round 14
// speedup vs baseline: 1.0201x; 1.0201x over previous
#include <cuda_runtime.h>
#include <math.h>
#include <stdint.h>

#define MARGIN            0.3f
#define CLST_SCALE        0.8f
#define SEP_SCALE         0.08f
#define DIV_SCALE         0.01f
#define CONTRASTIVE_SCALE 0.1f

#define MAXC 1024
#define MAXD 1024
#define MAXR 32
#define TPB  128
#define SPN_ROWS 10
#define SPN_D4   64
#define NMIN 2048
#define PROTO_GRID 296   // >= 148 so the low-grid SM issue throttle is off

struct Scratch {
    float cls_n[MAXC];
    float cls_sum[MAXC];
    float sep_sum[MAXC];
    float svec[MAXD];
    float div_sum;
    float ndv;
    float diag;
    float vc;
    unsigned int counter;
};
__device__ Scratch g;

__device__ __forceinline__ float inff() { return __int_as_float(0x7f800000); }

// ===========================================================================
// Kernel 1: proto classes (blocks 0..C-1) + mask count (block 0).
// Grid padded to PROTO_GRID to stay off the low-grid issue throttle.
// ===========================================================================
__global__ void __launch_bounds__(TPB, 10)
k_proto(const float* __restrict__ protos,
        const int*   __restrict__ pidx,
        const unsigned char* __restrict__ mask,
        int C, int T, int D) {
    const int tid  = threadIdx.x;
    const int warp = tid >> 5, lane = tid & 31;
    const int nwarp = TPB >> 5;
    const int c = blockIdx.x;

    if (c >= C) return;

    __shared__ float4 spn[SPN_ROWS * SPN_D4];
    __shared__ float s_inv[MAXR];
    __shared__ float s_rn2[MAXR];
    __shared__ int   s_rvalid[MAXR];
    __shared__ float s_pair;
    __shared__ float s_red[4];

    // mask dtype detection: uint8 all-true reads as 0x01010101 ints.
    int bad = 0;
    {
        const int* mi = (const int*)mask;
        const int n = T >> 2;
        for (int i = tid; i < n; i += TPB) {
            int v = mi[i];
            bad |= (v != 0 && v != 1);
        }
    }
    const int byte_mode = __syncthreads_or(bad);

    // block 0: global valid-mask count -> g.vc
    if (c == 0) {
        float cnt = 0.f;
        for (int t = tid; t < T; t += TPB) {
            int v = byte_mode ? (int)mask[t] : ((const int*)mask)[t];
            cnt += (v != 0) ? 1.f : 0.f;
        }
        #pragma unroll
        for (int o = 16; o; o >>= 1) cnt += __shfl_xor_sync(0xFFFFFFFFu, cnt, o);
        if (lane == 0) s_red[warp] = cnt;
        __syncthreads();
        if (tid == 0)
            atomicAdd(&g.vc, s_red[0] + s_red[1] + s_red[2] + s_red[3]);
    }

    int rs = pidx[2 * c];
    int re = (c + 1 < C) ? pidx[2 * (c + 1)] : T;
    if (re > T) re = T;
    if (rs < 0) rs = 0;
    int nr = re - rs;
    if (nr > MAXR) nr = MAXR;
    if (nr < 0) nr = 0;

    if (tid == 0) s_pair = 0.f;
    const bool d4ok = ((D & 3) == 0);
    const int  D4   = D >> 2;
    const float4* p4 = (const float4*)protos;
    const bool smok = d4ok && (nr <= SPN_ROWS) && (D4 <= SPN_D4);

    if (smok) {
        const int nv = nr * D4;
        for (int i = tid; i < nv; i += TPB) {
            int r = i / D4, d = i % D4;
            spn[r * SPN_D4 + d] = p4[(size_t)(rs + r) * D4 + d];
        }
        __syncthreads();

        for (int r = warp; r < nr; r += nwarp) {
            float ss = 0.f;
            for (int d = lane; d < D4; d += 32) {
                float4 x = spn[r * SPN_D4 + d];
                ss += x.x * x.x + x.y * x.y + x.z * x.z + x.w * x.w;
            }
            #pragma unroll
            for (int o = 16; o; o >>= 1) ss += __shfl_xor_sync(0xFFFFFFFFu, ss, o);
            float inv = 1.0f / fmaxf(sqrtf(ss), 1e-12f);
            if (lane == 0) {
                s_inv[r] = inv;
                s_rn2[r] = ss * inv * inv;
                int t = rs + r;
                int v = byte_mode ? (int)mask[t] : ((const int*)mask)[t];
                s_rvalid[r] = (v != 0);
            }
        }
        __syncthreads();

        for (int d = tid; d < D4; d += TPB) {
            float4 acc = make_float4(0.f, 0.f, 0.f, 0.f);
            for (int r = 0; r < nr; r++) {
                if (s_rvalid[r]) {
                    float4 x = spn[r * SPN_D4 + d];
                    float iv = s_inv[r];
                    acc.x += x.x * iv; acc.y += x.y * iv;
                    acc.z += x.z * iv; acc.w += x.w * iv;
                }
            }
            atomicAdd(&g.svec[4 * d + 0], acc.x);
            atomicAdd(&g.svec[4 * d + 1], acc.y);
            atomicAdd(&g.svec[4 * d + 2], acc.z);
            atomicAdd(&g.svec[4 * d + 3], acc.w);
        }
        if (tid == 0) {
            float ds = 0.f;
            for (int r = 0; r < nr; r++) if (s_rvalid[r]) ds += s_rn2[r];
            atomicAdd(&g.diag, ds);
        }

        const int npr = nr * (nr - 1) / 2;
        float local = 0.f;
        for (int k = warp; k < npr; k += nwarp) {
            int i = 0, rem = k;
            while (rem >= nr - 1 - i) { rem -= nr - 1 - i; i++; }
            int j = i + 1 + rem;
            float dot = 0.f;
            for (int d = lane; d < D4; d += 32) {
                float4 a = spn[i * SPN_D4 + d], b = spn[j * SPN_D4 + d];
                dot += a.x * b.x + a.y * b.y + a.z * b.z + a.w * b.w;
            }
            #pragma unroll
            for (int o = 16; o; o >>= 1) dot += __shfl_xor_sync(0xFFFFFFFFu, dot, o);
            if (lane == 0)
                local += 2.0f * fmaxf(dot * s_inv[i] * s_inv[j] - 0.5f, 0.f);
        }
        if (lane == 0 && local != 0.f) atomicAdd(&s_pair, local);
        __syncthreads();
    } else {
        for (int r = warp; r < nr; r += nwarp) {
            float ss = 0.f;
            const float* src = protos + (size_t)(rs + r) * D;
            for (int d = lane; d < D; d += 32) { float v = src[d]; ss += v * v; }
            #pragma unroll
            for (int o = 16; o; o >>= 1) ss += __shfl_xor_sync(0xFFFFFFFFu, ss, o);
            float inv = 1.0f / fmaxf(sqrtf(ss), 1e-12f);
            if (lane == 0) {
                s_inv[r] = inv;
                s_rn2[r] = ss * inv * inv;
                int t = rs + r;
                int v = byte_mode ? (int)mask[t] : ((const int*)mask)[t];
                s_rvalid[r] = (v != 0);
            }
        }
        __syncthreads();

        for (int d = tid; d < D; d += TPB) {
            float s = 0.f;
            for (int r = 0; r < nr; r++)
                if (s_rvalid[r])
                    s += protos[(size_t)(rs + r) * D + d] * s_inv[r];
            atomicAdd(&g.svec[d], s);
        }
        if (tid == 0) {
            float ds = 0.f;
            for (int r = 0; r < nr; r++) if (s_rvalid[r]) ds += s_rn2[r];
            atomicAdd(&g.diag, ds);
        }

        const int npr = nr * (nr - 1) / 2;
        float local = 0.f;
        for (int k = warp; k < npr; k += nwarp) {
            int i = 0, rem = k;
            while (rem >= nr - 1 - i) { rem -= nr - 1 - i; i++; }
            int j = i + 1 + rem;
            const float* ri = protos + (size_t)(rs + i) * D;
            const float* rj = protos + (size_t)(rs + j) * D;
            float dot = 0.f;
            for (int d = lane; d < D; d += 32) dot += ri[d] * rj[d];
            #pragma unroll
            for (int o = 16; o; o >>= 1) dot += __shfl_xor_sync(0xFFFFFFFFu, dot, o);
            if (lane == 0)
                local += 2.0f * fmaxf(dot * s_inv[i] * s_inv[j] - 0.5f, 0.f);
        }
        if (lane == 0 && local != 0.f) atomicAdd(&s_pair, local);
        __syncthreads();
    }

    if (tid == 0) {
        int cnt = pidx[2 * c + 1] - pidx[2 * c];
        if (cnt > 1) {
            float npf = (float)cnt * (float)(cnt - 1);
            atomicAdd(&g.div_sum, s_pair / fmaxf(npf, 1.0f));
            atomicAdd(&g.ndv, 1.0f);
        }
    }
}

// ===========================================================================
// Kernel 2: streaming min pass (at roofline) + last-block lean finalize.
// Runs after k_proto (stream order), so proto results are complete.
// ===========================================================================
__global__ void __launch_bounds__(TPB, 10)
k_min(const float* __restrict__ sims,
      const int*   __restrict__ labels,
      const int*   __restrict__ pidx,
      float* __restrict__ out,
      int B, int C, int P, int D, int fast_ok) {
    const int tid  = threadIdx.x;
    const int warp = tid >> 5, lane = tid & 31;
    const int nwarp = TPB >> 5;
    const int CP = C * P;
    const int gw = (int)blockIdx.x * nwarp + warp;
    const int stride = NMIN * nwarp;

    int okf = 1;
    for (int c = tid; c < C; c += TPB)
        okf &= ((pidx[2 * c + 1] - pidx[2 * c]) >= P);
    okf = __syncthreads_and(okf) & fast_ok;

    if (okf) {
        const int n4 = CP >> 2;
        const float NI = -inff();

        int lbls[4];
        #pragma unroll
        for (int r = 0; r < 4; r++) {
            int b = gw + r * stride;
            lbls[r] = (b < B) ? labels[b] : 0;
        }

        int r = 0;
        for (int b = gw; b < B; b += stride, r++) {
            const int lbl = (r < 4) ? lbls[r] : labels[b];
            const float4* s4 = (const float4*)(sims + (size_t)b * CP);

            float4 x[8];
            #pragma unroll
            for (int k = 0; k < 8; k++) {
                int vi = lane + 32 * k;
                x[k] = make_float4(NI, NI, NI, NI);
                if (vi < n4) x[k] = s4[vi];
            }

            const int lo = lbl * P, hi = lo + P;
            const int viL = lo >> 2, viH = (hi - 1) >> 2;
            float oth = NI;
            #pragma unroll
            for (int k = 0; k < 8; k++) {
                int vi = lane + 32 * k;
                float m4 = fmaxf(fmaxf(x[k].x, x[k].y), fmaxf(x[k].z, x[k].w));
                if (vi < viL || vi > viH) oth = fmaxf(oth, m4);
            }

            float own = NI;
            const int bidx = 4 * viL + lane;
            if (lane < 16 && bidx < CP) {
                float bv = sims[(size_t)b * CP + bidx];
                if (bidx >= lo && bidx < hi) own = bv;
                else if (bidx <= 4 * viH + 3) oth = fmaxf(oth, bv);
            }

            #pragma unroll
            for (int o = 16; o; o >>= 1) {
                own = fmaxf(own, __shfl_xor_sync(0xFFFFFFFFu, own, o));
                oth = fmaxf(oth, __shfl_xor_sync(0xFFFFFFFFu, oth, o));
            }
            if (lane == 0) {
                float ownd = 1.0f - own;
                float sep  = fmaxf(MARGIN - (1.0f - oth), 0.0f);
                atomicAdd(&g.cls_n[lbl],   1.0f);
                atomicAdd(&g.cls_sum[lbl], ownd);
                atomicAdd(&g.sep_sum[lbl], sep);
            }
        }
    } else {
        for (int b = gw; b < B; b += stride) {
            const float* src = sims + (size_t)b * CP;
            const int lbl = labels[b];
            float ownmax = -inff(), othermax = -inff();
            for (int c = lane; c < C; c += 32) {
                int cnt = pidx[2 * c + 1] - pidx[2 * c];
                if (cnt > P) cnt = P;
                float m = -inff();
                const float* pr = src + c * P;
                for (int p = 0; p < cnt; p++) m = fmaxf(m, pr[p]);
                if (c == lbl) ownmax = m;
                else          othermax = fmaxf(othermax, m);
            }
            #pragma unroll
            for (int o = 16; o; o >>= 1) {
                ownmax   = fmaxf(ownmax,   __shfl_xor_sync(0xFFFFFFFFu, ownmax,   o));
                othermax = fmaxf(othermax, __shfl_xor_sync(0xFFFFFFFFu, othermax, o));
            }
            if (lane == 0) {
                float own   = 1.0f - ownmax;
                float other = 1.0f - othermax;
                float sep   = fmaxf(MARGIN - other, 0.0f);
                atomicAdd(&g.cls_n[lbl],   1.0f);
                atomicAdd(&g.cls_sum[lbl], own);
                atomicAdd(&g.sep_sum[lbl], sep);
            }
        }
    }

    // ---- last-block lean finalize (grid = 2048, never throttled) ----------
    __threadfence();
    __shared__ unsigned int s_ord;
    if (tid == 0) s_ord = atomicAdd(&g.counter, 1u);
    __syncthreads();
    if (s_ord != (unsigned)(NMIN - 1)) return;
    if (warp != 0) return;
    __threadfence();

    float ca = 0.f, sa = 0.f, nv = 0.f;
    for (int cc = lane; cc < C; cc += 32) {
        float n = g.cls_n[cc];
        if (n > 0.f) {
            nv += 1.f;
            float nm = fmaxf(n, 1.f);
            ca += (1.0f / sqrtf(n + 1e-6f)) * (g.cls_sum[cc] / nm);
            sa += g.sep_sum[cc] / nm;
        }
    }
    float sn = 0.f;
    for (int d = lane; d < D; d += 32) { float v = g.svec[d]; sn += v * v; }

    #pragma unroll
    for (int o = 16; o; o >>= 1) {
        ca += __shfl_xor_sync(0xFFFFFFFFu, ca, o);
        sa += __shfl_xor_sync(0xFFFFFFFFu, sa, o);
        nv += __shfl_xor_sync(0xFFFFFFFFu, nv, o);
        sn += __shfl_xor_sync(0xFFFFFFFFu, sn, o);
    }

    if (lane == 0) {
        float vc      = g.vc;
        float nvalid  = fmaxf(nv, 1.f);
        float cluster = ca / nvalid * CLST_SCALE;
        float sep     = sa / nvalid * SEP_SCALE;
        float divl    = g.div_sum / fmaxf(g.ndv, 1.f) * DIV_SCALE;
        float nvp     = fmaxf(vc * vc - vc, 1.f);
        float contr   = (sn - g.diag) / nvp * CONTRASTIVE_SCALE;
        out[0] = cluster;
        out[1] = sep;
        out[2] = divl;
        out[3] = contr;
        out[4] = cluster + sep + divl + contr;
    }
}

extern "C" void kernel_launch(void* const* d_in, const int* in_sizes, int n_in,
                              void* d_out, int out_size) {
    const float* sims   = (const float*)d_in[0];
    const int*   labels = (const int*)  d_in[1];
    const float* protos = (const float*)d_in[2];
    const int*   pidx   = (const int*)  d_in[3];
    const unsigned char* mask = (const unsigned char*)d_in[4];

    const int B = in_sizes[1];
    const int C = in_sizes[3] / 2;
    const int T = in_sizes[4];
    const int D = in_sizes[2] / T;
    const int P = in_sizes[0] / (B * C);
    float* out = (float*)d_out;

    void* gp = nullptr;
    cudaGetSymbolAddress(&gp, g);
    cudaMemsetAsync(gp, 0, sizeof(Scratch), 0);

    const int CP = C * P;
    const int fast_ok = (((CP & 3) == 0) && (CP <= 1024) && (P <= 13)) ? 1 : 0;

    int pg = PROTO_GRID;
    if (pg < C) pg = C;            // always cover all classes
    k_proto<<<pg, TPB>>>(protos, pidx, mask, C, T, D);
    k_min<<<NMIN, TPB>>>(sims, labels, pidx, out, B, C, P, D, fast_ok);
}

// round 15
// speedup vs baseline: 1.6222x; 1.5903x over previous
#include <cuda_runtime.h>
#include <math.h>
#include <stdint.h>

#define MARGIN            0.3f
#define CLST_SCALE        0.8f
#define SEP_SCALE         0.08f
#define DIV_SCALE         0.01f
#define CONTRASTIVE_SCALE 0.1f

#define MAXC 1024
#define MAXD 1024
#define MAXR 32
#define TPB  128
#define SPN_ROWS 10
#define SPN_D4   64
#define NMIN 2048

struct Scratch {
    float cls_n[MAXC];
    float cls_sum[MAXC];
    float sep_sum[MAXC];
    float svec[MAXD];
    float div_sum;
    float ndv;
    float diag;
    float vc;
};
__device__ Scratch g;

__device__ __forceinline__ float inff() { return __int_as_float(0x7f800000); }

// ===========================================================================
// Kernel 1 (fused): proto blocks [0,C) + streaming min blocks [C, C+NMIN).
// NO threadfence, NO counter, NO finalize tail — nothing but the work.
// ===========================================================================
__global__ void __launch_bounds__(TPB, 10)
k_main(const float* __restrict__ sims,
       const int*   __restrict__ labels,
       const float* __restrict__ protos,
       const int*   __restrict__ pidx,
       const unsigned char* __restrict__ mask,
       int B, int C, int P, int T, int D, int fast_ok) {
    const int tid  = threadIdx.x;
    const int warp = tid >> 5, lane = tid & 31;
    const int nwarp = TPB >> 5;

    if ((int)blockIdx.x < C) {
        // =================== proto block for class c =======================
        __shared__ float4 spn[SPN_ROWS * SPN_D4];
        __shared__ float s_inv[MAXR];
        __shared__ float s_rn2[MAXR];
        __shared__ int   s_rvalid[MAXR];
        __shared__ float s_pair;
        __shared__ float s_red[4];

        // mask dtype detection: uint8 all-true reads as 0x01010101 ints.
        int bad = 0;
        {
            const int* mi = (const int*)mask;
            const int n = T >> 2;
            for (int i = tid; i < n; i += TPB) {
                int v = mi[i];
                bad |= (v != 0 && v != 1);
            }
        }
        const int byte_mode = __syncthreads_or(bad);

        const int c = blockIdx.x;

        // block 0: global valid-mask count -> g.vc
        if (c == 0) {
            float cnt = 0.f;
            for (int t = tid; t < T; t += TPB) {
                int v = byte_mode ? (int)mask[t] : ((const int*)mask)[t];
                cnt += (v != 0) ? 1.f : 0.f;
            }
            #pragma unroll
            for (int o = 16; o; o >>= 1) cnt += __shfl_xor_sync(0xFFFFFFFFu, cnt, o);
            if (lane == 0) s_red[warp] = cnt;
            __syncthreads();
            if (tid == 0)
                atomicAdd(&g.vc, s_red[0] + s_red[1] + s_red[2] + s_red[3]);
        }

        int rs = pidx[2 * c];
        int re = (c + 1 < C) ? pidx[2 * (c + 1)] : T;
        if (re > T) re = T;
        if (rs < 0) rs = 0;
        int nr = re - rs;
        if (nr > MAXR) nr = MAXR;
        if (nr < 0) nr = 0;

        if (tid == 0) s_pair = 0.f;
        const bool d4ok = ((D & 3) == 0);
        const int  D4   = D >> 2;
        const float4* p4 = (const float4*)protos;
        const bool smok = d4ok && (nr <= SPN_ROWS) && (D4 <= SPN_D4);

        if (smok) {
            const int nv = nr * D4;
            for (int i = tid; i < nv; i += TPB) {
                int r = i / D4, d = i % D4;
                spn[r * SPN_D4 + d] = p4[(size_t)(rs + r) * D4 + d];
            }
            __syncthreads();

            for (int r = warp; r < nr; r += nwarp) {
                float ss = 0.f;
                for (int d = lane; d < D4; d += 32) {
                    float4 x = spn[r * SPN_D4 + d];
                    ss += x.x * x.x + x.y * x.y + x.z * x.z + x.w * x.w;
                }
                #pragma unroll
                for (int o = 16; o; o >>= 1) ss += __shfl_xor_sync(0xFFFFFFFFu, ss, o);
                float inv = 1.0f / fmaxf(sqrtf(ss), 1e-12f);
                if (lane == 0) {
                    s_inv[r] = inv;
                    s_rn2[r] = ss * inv * inv;
                    int t = rs + r;
                    int v = byte_mode ? (int)mask[t] : ((const int*)mask)[t];
                    s_rvalid[r] = (v != 0);
                }
            }
            __syncthreads();

            for (int d = tid; d < D4; d += TPB) {
                float4 acc = make_float4(0.f, 0.f, 0.f, 0.f);
                for (int r = 0; r < nr; r++) {
                    if (s_rvalid[r]) {
                        float4 x = spn[r * SPN_D4 + d];
                        float iv = s_inv[r];
                        acc.x += x.x * iv; acc.y += x.y * iv;
                        acc.z += x.z * iv; acc.w += x.w * iv;
                    }
                }
                atomicAdd(&g.svec[4 * d + 0], acc.x);
                atomicAdd(&g.svec[4 * d + 1], acc.y);
                atomicAdd(&g.svec[4 * d + 2], acc.z);
                atomicAdd(&g.svec[4 * d + 3], acc.w);
            }
            if (tid == 0) {
                float ds = 0.f;
                for (int r = 0; r < nr; r++) if (s_rvalid[r]) ds += s_rn2[r];
                atomicAdd(&g.diag, ds);
            }

            const int npr = nr * (nr - 1) / 2;
            float local = 0.f;
            for (int k = warp; k < npr; k += nwarp) {
                int i = 0, rem = k;
                while (rem >= nr - 1 - i) { rem -= nr - 1 - i; i++; }
                int j = i + 1 + rem;
                float dot = 0.f;
                for (int d = lane; d < D4; d += 32) {
                    float4 a = spn[i * SPN_D4 + d], b = spn[j * SPN_D4 + d];
                    dot += a.x * b.x + a.y * b.y + a.z * b.z + a.w * b.w;
                }
                #pragma unroll
                for (int o = 16; o; o >>= 1) dot += __shfl_xor_sync(0xFFFFFFFFu, dot, o);
                if (lane == 0)
                    local += 2.0f * fmaxf(dot * s_inv[i] * s_inv[j] - 0.5f, 0.f);
            }
            if (lane == 0 && local != 0.f) atomicAdd(&s_pair, local);
            __syncthreads();
        } else {
            for (int r = warp; r < nr; r += nwarp) {
                float ss = 0.f;
                const float* src = protos + (size_t)(rs + r) * D;
                for (int d = lane; d < D; d += 32) { float v = src[d]; ss += v * v; }
                #pragma unroll
                for (int o = 16; o; o >>= 1) ss += __shfl_xor_sync(0xFFFFFFFFu, ss, o);
                float inv = 1.0f / fmaxf(sqrtf(ss), 1e-12f);
                if (lane == 0) {
                    s_inv[r] = inv;
                    s_rn2[r] = ss * inv * inv;
                    int t = rs + r;
                    int v = byte_mode ? (int)mask[t] : ((const int*)mask)[t];
                    s_rvalid[r] = (v != 0);
                }
            }
            __syncthreads();

            for (int d = tid; d < D; d += TPB) {
                float s = 0.f;
                for (int r = 0; r < nr; r++)
                    if (s_rvalid[r])
                        s += protos[(size_t)(rs + r) * D + d] * s_inv[r];
                atomicAdd(&g.svec[d], s);
            }
            if (tid == 0) {
                float ds = 0.f;
                for (int r = 0; r < nr; r++) if (s_rvalid[r]) ds += s_rn2[r];
                atomicAdd(&g.diag, ds);
            }

            const int npr = nr * (nr - 1) / 2;
            float local = 0.f;
            for (int k = warp; k < npr; k += nwarp) {
                int i = 0, rem = k;
                while (rem >= nr - 1 - i) { rem -= nr - 1 - i; i++; }
                int j = i + 1 + rem;
                const float* ri = protos + (size_t)(rs + i) * D;
                const float* rj = protos + (size_t)(rs + j) * D;
                float dot = 0.f;
                for (int d = lane; d < D; d += 32) dot += ri[d] * rj[d];
                #pragma unroll
                for (int o = 16; o; o >>= 1) dot += __shfl_xor_sync(0xFFFFFFFFu, dot, o);
                if (lane == 0)
                    local += 2.0f * fmaxf(dot * s_inv[i] * s_inv[j] - 0.5f, 0.f);
            }
            if (lane == 0 && local != 0.f) atomicAdd(&s_pair, local);
            __syncthreads();
        }

        if (tid == 0) {
            int cnt = pidx[2 * c + 1] - pidx[2 * c];
            if (cnt > 1) {
                float npf = (float)cnt * (float)(cnt - 1);
                atomicAdd(&g.div_sum, s_pair / fmaxf(npf, 1.0f));
                atomicAdd(&g.ndv, 1.0f);
            }
        }
    } else {
        // =================== streaming min blocks ==========================
        const int CP = C * P;
        const int gw = ((int)blockIdx.x - C) * nwarp + warp;
        const int stride = NMIN * nwarp;

        int okf = 1;
        for (int c = tid; c < C; c += TPB)
            okf &= ((pidx[2 * c + 1] - pidx[2 * c]) >= P);
        okf = __syncthreads_and(okf) & fast_ok;

        if (okf) {
            const int n4 = CP >> 2;
            const float NI = -inff();

            int lbls[4];
            #pragma unroll
            for (int r = 0; r < 4; r++) {
                int b = gw + r * stride;
                lbls[r] = (b < B) ? labels[b] : 0;
            }

            int r = 0;
            for (int b = gw; b < B; b += stride, r++) {
                const int lbl = (r < 4) ? lbls[r] : labels[b];
                const float4* s4 = (const float4*)(sims + (size_t)b * CP);

                float4 x[8];
                #pragma unroll
                for (int k = 0; k < 8; k++) {
                    int vi = lane + 32 * k;
                    x[k] = make_float4(NI, NI, NI, NI);
                    if (vi < n4) x[k] = s4[vi];
                }

                const int lo = lbl * P, hi = lo + P;
                const int viL = lo >> 2, viH = (hi - 1) >> 2;
                float oth = NI;
                #pragma unroll
                for (int k = 0; k < 8; k++) {
                    int vi = lane + 32 * k;
                    float m4 = fmaxf(fmaxf(x[k].x, x[k].y), fmaxf(x[k].z, x[k].w));
                    if (vi < viL || vi > viH) oth = fmaxf(oth, m4);
                }

                float own = NI;
                const int bidx = 4 * viL + lane;
                if (lane < 16 && bidx < CP) {
                    float bv = sims[(size_t)b * CP + bidx];
                    if (bidx >= lo && bidx < hi) own = bv;
                    else if (bidx <= 4 * viH + 3) oth = fmaxf(oth, bv);
                }

                #pragma unroll
                for (int o = 16; o; o >>= 1) {
                    own = fmaxf(own, __shfl_xor_sync(0xFFFFFFFFu, own, o));
                    oth = fmaxf(oth, __shfl_xor_sync(0xFFFFFFFFu, oth, o));
                }
                if (lane == 0) {
                    float ownd = 1.0f - own;
                    float sep  = fmaxf(MARGIN - (1.0f - oth), 0.0f);
                    atomicAdd(&g.cls_n[lbl],   1.0f);
                    atomicAdd(&g.cls_sum[lbl], ownd);
                    atomicAdd(&g.sep_sum[lbl], sep);
                }
            }
        } else {
            for (int b = gw; b < B; b += stride) {
                const float* src = sims + (size_t)b * CP;
                const int lbl = labels[b];
                float ownmax = -inff(), othermax = -inff();
                for (int c = lane; c < C; c += 32) {
                    int cnt = pidx[2 * c + 1] - pidx[2 * c];
                    if (cnt > P) cnt = P;
                    float m = -inff();
                    const float* pr = src + c * P;
                    for (int p = 0; p < cnt; p++) m = fmaxf(m, pr[p]);
                    if (c == lbl) ownmax = m;
                    else          othermax = fmaxf(othermax, m);
                }
                #pragma unroll
                for (int o = 16; o; o >>= 1) {
                    ownmax   = fmaxf(ownmax,   __shfl_xor_sync(0xFFFFFFFFu, ownmax,   o));
                    othermax = fmaxf(othermax, __shfl_xor_sync(0xFFFFFFFFu, othermax, o));
                }
                if (lane == 0) {
                    float own   = 1.0f - ownmax;
                    float other = 1.0f - othermax;
                    float sep   = fmaxf(MARGIN - other, 0.0f);
                    atomicAdd(&g.cls_n[lbl],   1.0f);
                    atomicAdd(&g.cls_sum[lbl], own);
                    atomicAdd(&g.sep_sum[lbl], sep);
                }
            }
        }
    }
}

// ===========================================================================
// Kernel 2: finalize. Grid = 148 (>= throttle threshold); block 0 works,
// the rest exit. Ordering guaranteed by stream serialization.
// ===========================================================================
__global__ void __launch_bounds__(TPB)
k_final(float* __restrict__ out, int C, int D) {
    if (blockIdx.x != 0) return;
    const int tid  = threadIdx.x;
    const int warp = tid >> 5, lane = tid & 31;
    __shared__ float s_red[4][4];

    float ca = 0.f, sa = 0.f, nv = 0.f;
    for (int c = tid; c < C; c += TPB) {
        float n = g.cls_n[c];
        if (n > 0.f) {
            nv += 1.f;
            float nm = fmaxf(n, 1.f);
            ca += (1.0f / sqrtf(n + 1e-6f)) * (g.cls_sum[c] / nm);
            sa += g.sep_sum[c] / nm;
        }
    }
    float sn = 0.f;
    for (int d = tid; d < D; d += TPB) { float v = g.svec[d]; sn += v * v; }

    #pragma unroll
    for (int o = 16; o; o >>= 1) {
        ca += __shfl_xor_sync(0xFFFFFFFFu, ca, o);
        sa += __shfl_xor_sync(0xFFFFFFFFu, sa, o);
        nv += __shfl_xor_sync(0xFFFFFFFFu, nv, o);
        sn += __shfl_xor_sync(0xFFFFFFFFu, sn, o);
    }
    if (lane == 0) {
        s_red[warp][0] = ca; s_red[warp][1] = sa;
        s_red[warp][2] = nv; s_red[warp][3] = sn;
    }
    __syncthreads();

    if (tid == 0) {
        ca = s_red[0][0] + s_red[1][0] + s_red[2][0] + s_red[3][0];
        sa = s_red[0][1] + s_red[1][1] + s_red[2][1] + s_red[3][1];
        nv = s_red[0][2] + s_red[1][2] + s_red[2][2] + s_red[3][2];
        sn = s_red[0][3] + s_red[1][3] + s_red[2][3] + s_red[3][3];

        float vc      = g.vc;
        float nvalid  = fmaxf(nv, 1.f);
        float cluster = ca / nvalid * CLST_SCALE;
        float sep     = sa / nvalid * SEP_SCALE;
        float divl    = g.div_sum / fmaxf(g.ndv, 1.f) * DIV_SCALE;
        float nvp     = fmaxf(vc * vc - vc, 1.f);
        float contr   = (sn - g.diag) / nvp * CONTRASTIVE_SCALE;
        out[0] = cluster;
        out[1] = sep;
        out[2] = divl;
        out[3] = contr;
        out[4] = cluster + sep + divl + contr;
    }
}

extern "C" void kernel_launch(void* const* d_in, const int* in_sizes, int n_in,
                              void* d_out, int out_size) {
    const float* sims   = (const float*)d_in[0];
    const int*   labels = (const int*)  d_in[1];
    const float* protos = (const float*)d_in[2];
    const int*   pidx   = (const int*)  d_in[3];
    const unsigned char* mask = (const unsigned char*)d_in[4];

    const int B = in_sizes[1];
    const int C = in_sizes[3] / 2;
    const int T = in_sizes[4];
    const int D = in_sizes[2] / T;
    const int P = in_sizes[0] / (B * C);
    float* out = (float*)d_out;

    void* gp = nullptr;
    cudaGetSymbolAddress(&gp, g);
    cudaMemsetAsync(gp, 0, sizeof(Scratch), 0);

    const int CP = C * P;
    const int fast_ok = (((CP & 3) == 0) && (CP <= 1024) && (P <= 13)) ? 1 : 0;

    k_main<<<C + NMIN, TPB>>>(sims, labels, protos, pidx, mask,
                              B, C, P, T, D, fast_ok);
    k_final<<<148, TPB>>>(out, C, D);
}

// round 16
// speedup vs baseline: 1.7805x; 1.0976x over previous
#include <cuda_runtime.h>
#include <math.h>
#include <stdint.h>

#define MARGIN            0.3f
#define CLST_SCALE        0.8f
#define SEP_SCALE         0.08f
#define DIV_SCALE         0.01f
#define CONTRASTIVE_SCALE 0.1f

#define MAXC 1024
#define MAXD 1024
#define MAXR 32
#define TPB  128
#define SPN_ROWS 10
#define SPN_D4   64
#define NMIN 2048

struct Scratch {
    float cls_n[MAXC];
    float cls_sum[MAXC];
    float sep_sum[MAXC];
    float svec[MAXD];
    float div_sum;
    float ndv;
    float diag;
    float vc;
};
__device__ Scratch g;    // zero-initialized at load; k_final re-zeros after use

__device__ __forceinline__ float inff() { return __int_as_float(0x7f800000); }

// ===========================================================================
// Kernel 1 (fused): proto blocks [0,C) + streaming min blocks [C, C+NMIN).
// No fences, no counters, no finalize tail.
// ===========================================================================
__global__ void __launch_bounds__(TPB, 10)
k_main(const float* __restrict__ sims,
       const int*   __restrict__ labels,
       const float* __restrict__ protos,
       const int*   __restrict__ pidx,
       const unsigned char* __restrict__ mask,
       int B, int C, int P, int T, int D, int fast_ok) {
    const int tid  = threadIdx.x;
    const int warp = tid >> 5, lane = tid & 31;
    const int nwarp = TPB >> 5;

    if ((int)blockIdx.x < C) {
        // =================== proto block for class c =======================
        __shared__ float4 spn[SPN_ROWS * SPN_D4];
        __shared__ float s_inv[MAXR];
        __shared__ float s_rn2[MAXR];
        __shared__ int   s_rvalid[MAXR];
        __shared__ float s_pair;
        __shared__ float s_red[4];

        // mask dtype detection: uint8 all-true reads as 0x01010101 ints.
        int bad = 0;
        {
            const int* mi = (const int*)mask;
            const int n = T >> 2;
            for (int i = tid; i < n; i += TPB) {
                int v = mi[i];
                bad |= (v != 0 && v != 1);
            }
        }
        const int byte_mode = __syncthreads_or(bad);

        const int c = blockIdx.x;

        // block 0: global valid-mask count -> g.vc
        if (c == 0) {
            float cnt = 0.f;
            for (int t = tid; t < T; t += TPB) {
                int v = byte_mode ? (int)mask[t] : ((const int*)mask)[t];
                cnt += (v != 0) ? 1.f : 0.f;
            }
            #pragma unroll
            for (int o = 16; o; o >>= 1) cnt += __shfl_xor_sync(0xFFFFFFFFu, cnt, o);
            if (lane == 0) s_red[warp] = cnt;
            __syncthreads();
            if (tid == 0)
                atomicAdd(&g.vc, s_red[0] + s_red[1] + s_red[2] + s_red[3]);
        }

        int rs = pidx[2 * c];
        int re = (c + 1 < C) ? pidx[2 * (c + 1)] : T;
        if (re > T) re = T;
        if (rs < 0) rs = 0;
        int nr = re - rs;
        if (nr > MAXR) nr = MAXR;
        if (nr < 0) nr = 0;

        if (tid == 0) s_pair = 0.f;
        const bool d4ok = ((D & 3) == 0);
        const int  D4   = D >> 2;
        const float4* p4 = (const float4*)protos;
        const bool smok = d4ok && (nr <= SPN_ROWS) && (D4 <= SPN_D4);

        if (smok) {
            const int nv = nr * D4;
            for (int i = tid; i < nv; i += TPB) {
                int r = i / D4, d = i % D4;
                spn[r * SPN_D4 + d] = p4[(size_t)(rs + r) * D4 + d];
            }
            __syncthreads();

            for (int r = warp; r < nr; r += nwarp) {
                float ss = 0.f;
                for (int d = lane; d < D4; d += 32) {
                    float4 x = spn[r * SPN_D4 + d];
                    ss += x.x * x.x + x.y * x.y + x.z * x.z + x.w * x.w;
                }
                #pragma unroll
                for (int o = 16; o; o >>= 1) ss += __shfl_xor_sync(0xFFFFFFFFu, ss, o);
                float inv = 1.0f / fmaxf(sqrtf(ss), 1e-12f);
                if (lane == 0) {
                    s_inv[r] = inv;
                    s_rn2[r] = ss * inv * inv;
                    int t = rs + r;
                    int v = byte_mode ? (int)mask[t] : ((const int*)mask)[t];
                    s_rvalid[r] = (v != 0);
                }
            }
            __syncthreads();

            for (int d = tid; d < D4; d += TPB) {
                float4 acc = make_float4(0.f, 0.f, 0.f, 0.f);
                for (int r = 0; r < nr; r++) {
                    if (s_rvalid[r]) {
                        float4 x = spn[r * SPN_D4 + d];
                        float iv = s_inv[r];
                        acc.x += x.x * iv; acc.y += x.y * iv;
                        acc.z += x.z * iv; acc.w += x.w * iv;
                    }
                }
                atomicAdd(&g.svec[4 * d + 0], acc.x);
                atomicAdd(&g.svec[4 * d + 1], acc.y);
                atomicAdd(&g.svec[4 * d + 2], acc.z);
                atomicAdd(&g.svec[4 * d + 3], acc.w);
            }
            if (tid == 0) {
                float ds = 0.f;
                for (int r = 0; r < nr; r++) if (s_rvalid[r]) ds += s_rn2[r];
                atomicAdd(&g.diag, ds);
            }

            const int npr = nr * (nr - 1) / 2;
            float local = 0.f;
            for (int k = warp; k < npr; k += nwarp) {
                int i = 0, rem = k;
                while (rem >= nr - 1 - i) { rem -= nr - 1 - i; i++; }
                int j = i + 1 + rem;
                float dot = 0.f;
                for (int d = lane; d < D4; d += 32) {
                    float4 a = spn[i * SPN_D4 + d], b = spn[j * SPN_D4 + d];
                    dot += a.x * b.x + a.y * b.y + a.z * b.z + a.w * b.w;
                }
                #pragma unroll
                for (int o = 16; o; o >>= 1) dot += __shfl_xor_sync(0xFFFFFFFFu, dot, o);
                if (lane == 0)
                    local += 2.0f * fmaxf(dot * s_inv[i] * s_inv[j] - 0.5f, 0.f);
            }
            if (lane == 0 && local != 0.f) atomicAdd(&s_pair, local);
            __syncthreads();
        } else {
            for (int r = warp; r < nr; r += nwarp) {
                float ss = 0.f;
                const float* src = protos + (size_t)(rs + r) * D;
                for (int d = lane; d < D; d += 32) { float v = src[d]; ss += v * v; }
                #pragma unroll
                for (int o = 16; o; o >>= 1) ss += __shfl_xor_sync(0xFFFFFFFFu, ss, o);
                float inv = 1.0f / fmaxf(sqrtf(ss), 1e-12f);
                if (lane == 0) {
                    s_inv[r] = inv;
                    s_rn2[r] = ss * inv * inv;
                    int t = rs + r;
                    int v = byte_mode ? (int)mask[t] : ((const int*)mask)[t];
                    s_rvalid[r] = (v != 0);
                }
            }
            __syncthreads();

            for (int d = tid; d < D; d += TPB) {
                float s = 0.f;
                for (int r = 0; r < nr; r++)
                    if (s_rvalid[r])
                        s += protos[(size_t)(rs + r) * D + d] * s_inv[r];
                atomicAdd(&g.svec[d], s);
            }
            if (tid == 0) {
                float ds = 0.f;
                for (int r = 0; r < nr; r++) if (s_rvalid[r]) ds += s_rn2[r];
                atomicAdd(&g.diag, ds);
            }

            const int npr = nr * (nr - 1) / 2;
            float local = 0.f;
            for (int k = warp; k < npr; k += nwarp) {
                int i = 0, rem = k;
                while (rem >= nr - 1 - i) { rem -= nr - 1 - i; i++; }
                int j = i + 1 + rem;
                const float* ri = protos + (size_t)(rs + i) * D;
                const float* rj = protos + (size_t)(rs + j) * D;
                float dot = 0.f;
                for (int d = lane; d < D; d += 32) dot += ri[d] * rj[d];
                #pragma unroll
                for (int o = 16; o; o >>= 1) dot += __shfl_xor_sync(0xFFFFFFFFu, dot, o);
                if (lane == 0)
                    local += 2.0f * fmaxf(dot * s_inv[i] * s_inv[j] - 0.5f, 0.f);
            }
            if (lane == 0 && local != 0.f) atomicAdd(&s_pair, local);
            __syncthreads();
        }

        if (tid == 0) {
            int cnt = pidx[2 * c + 1] - pidx[2 * c];
            if (cnt > 1) {
                float npf = (float)cnt * (float)(cnt - 1);
                atomicAdd(&g.div_sum, s_pair / fmaxf(npf, 1.0f));
                atomicAdd(&g.ndv, 1.0f);
            }
        }
    } else {
        // =================== streaming min blocks ==========================
        const int CP = C * P;
        const int gw = ((int)blockIdx.x - C) * nwarp + warp;
        const int stride = NMIN * nwarp;

        int okf = 1;
        for (int c = tid; c < C; c += TPB)
            okf &= ((pidx[2 * c + 1] - pidx[2 * c]) >= P);
        okf = __syncthreads_and(okf) & fast_ok;

        if (okf) {
            const int n4 = CP >> 2;
            const float NI = -inff();

            int lbls[4];
            #pragma unroll
            for (int r = 0; r < 4; r++) {
                int b = gw + r * stride;
                lbls[r] = (b < B) ? labels[b] : 0;
            }

            int r = 0;
            for (int b = gw; b < B; b += stride, r++) {
                const int lbl = (r < 4) ? lbls[r] : labels[b];
                const float4* s4 = (const float4*)(sims + (size_t)b * CP);

                float4 x[8];
                #pragma unroll
                for (int k = 0; k < 8; k++) {
                    int vi = lane + 32 * k;
                    x[k] = make_float4(NI, NI, NI, NI);
                    if (vi < n4) x[k] = s4[vi];
                }

                const int lo = lbl * P, hi = lo + P;
                const int viL = lo >> 2, viH = (hi - 1) >> 2;
                float oth = NI;
                #pragma unroll
                for (int k = 0; k < 8; k++) {
                    int vi = lane + 32 * k;
                    float m4 = fmaxf(fmaxf(x[k].x, x[k].y), fmaxf(x[k].z, x[k].w));
                    if (vi < viL || vi > viH) oth = fmaxf(oth, m4);
                }

                float own = NI;
                const int bidx = 4 * viL + lane;
                if (lane < 16 && bidx < CP) {
                    float bv = sims[(size_t)b * CP + bidx];
                    if (bidx >= lo && bidx < hi) own = bv;
                    else if (bidx <= 4 * viH + 3) oth = fmaxf(oth, bv);
                }

                #pragma unroll
                for (int o = 16; o; o >>= 1) {
                    own = fmaxf(own, __shfl_xor_sync(0xFFFFFFFFu, own, o));
                    oth = fmaxf(oth, __shfl_xor_sync(0xFFFFFFFFu, oth, o));
                }
                if (lane == 0) {
                    float ownd = 1.0f - own;
                    float sep  = fmaxf(MARGIN - (1.0f - oth), 0.0f);
                    atomicAdd(&g.cls_n[lbl],   1.0f);
                    atomicAdd(&g.cls_sum[lbl], ownd);
                    atomicAdd(&g.sep_sum[lbl], sep);
                }
            }
        } else {
            for (int b = gw; b < B; b += stride) {
                const float* src = sims + (size_t)b * CP;
                const int lbl = labels[b];
                float ownmax = -inff(), othermax = -inff();
                for (int c = lane; c < C; c += 32) {
                    int cnt = pidx[2 * c + 1] - pidx[2 * c];
                    if (cnt > P) cnt = P;
                    float m = -inff();
                    const float* pr = src + c * P;
                    for (int p = 0; p < cnt; p++) m = fmaxf(m, pr[p]);
                    if (c == lbl) ownmax = m;
                    else          othermax = fmaxf(othermax, m);
                }
                #pragma unroll
                for (int o = 16; o; o >>= 1) {
                    ownmax   = fmaxf(ownmax,   __shfl_xor_sync(0xFFFFFFFFu, ownmax,   o));
                    othermax = fmaxf(othermax, __shfl_xor_sync(0xFFFFFFFFu, othermax, o));
                }
                if (lane == 0) {
                    float own   = 1.0f - ownmax;
                    float other = 1.0f - othermax;
                    float sep   = fmaxf(MARGIN - other, 0.0f);
                    atomicAdd(&g.cls_n[lbl],   1.0f);
                    atomicAdd(&g.cls_sum[lbl], own);
                    atomicAdd(&g.sep_sum[lbl], sep);
                }
            }
        }
    }
}

// ===========================================================================
// Kernel 2: finalize (PDL secondary). Grid = 148; block 0 works, rest exit
// after the dependency sync. Reads scratch, writes 5 outputs, then re-zeros
// the scratch so the next graph replay starts clean (initial state is the
// zero-initialized __device__ image).
// ===========================================================================
__global__ void __launch_bounds__(TPB)
k_final(float* __restrict__ out, int C, int D) {
#if __CUDA_ARCH__ >= 900
    cudaGridDependencySynchronize();   // wait for k_main completion (PDL)
#endif
    if (blockIdx.x != 0) return;
    const int tid  = threadIdx.x;
    const int warp = tid >> 5, lane = tid & 31;
    __shared__ float s_red[4][4];

    float ca = 0.f, sa = 0.f, nv = 0.f;
    for (int c = tid; c < C; c += TPB) {
        float n = g.cls_n[c];
        if (n > 0.f) {
            nv += 1.f;
            float nm = fmaxf(n, 1.f);
            ca += (1.0f / sqrtf(n + 1e-6f)) * (g.cls_sum[c] / nm);
            sa += g.sep_sum[c] / nm;
        }
    }
    float sn = 0.f;
    for (int d = tid; d < D; d += TPB) { float v = g.svec[d]; sn += v * v; }

    #pragma unroll
    for (int o = 16; o; o >>= 1) {
        ca += __shfl_xor_sync(0xFFFFFFFFu, ca, o);
        sa += __shfl_xor_sync(0xFFFFFFFFu, sa, o);
        nv += __shfl_xor_sync(0xFFFFFFFFu, nv, o);
        sn += __shfl_xor_sync(0xFFFFFFFFu, sn, o);
    }
    if (lane == 0) {
        s_red[warp][0] = ca; s_red[warp][1] = sa;
        s_red[warp][2] = nv; s_red[warp][3] = sn;
    }
    __syncthreads();

    if (tid == 0) {
        ca = s_red[0][0] + s_red[1][0] + s_red[2][0] + s_red[3][0];
        sa = s_red[0][1] + s_red[1][1] + s_red[2][1] + s_red[3][1];
        nv = s_red[0][2] + s_red[1][2] + s_red[2][2] + s_red[3][2];
        sn = s_red[0][3] + s_red[1][3] + s_red[2][3] + s_red[3][3];

        float vc      = g.vc;
        float nvalid  = fmaxf(nv, 1.f);
        float cluster = ca / nvalid * CLST_SCALE;
        float sep     = sa / nvalid * SEP_SCALE;
        float divl    = g.div_sum / fmaxf(g.ndv, 1.f) * DIV_SCALE;
        float nvp     = fmaxf(vc * vc - vc, 1.f);
        float contr   = (sn - g.diag) / nvp * CONTRASTIVE_SCALE;
        out[0] = cluster;
        out[1] = sep;
        out[2] = divl;
        out[3] = contr;
        out[4] = cluster + sep + divl + contr;
    }
    __syncthreads();

    // re-zero scratch for the next replay (replaces the memset node)
    float* gz = (float*)&g;
    const int nz = (int)(sizeof(Scratch) / sizeof(float));
    for (int i = tid; i < nz; i += TPB) gz[i] = 0.f;
}

extern "C" void kernel_launch(void* const* d_in, const int* in_sizes, int n_in,
                              void* d_out, int out_size) {
    const float* sims   = (const float*)d_in[0];
    const int*   labels = (const int*)  d_in[1];
    const float* protos = (const float*)d_in[2];
    const int*   pidx   = (const int*)  d_in[3];
    const unsigned char* mask = (const unsigned char*)d_in[4];

    const int B = in_sizes[1];
    const int C = in_sizes[3] / 2;
    const int T = in_sizes[4];
    const int D = in_sizes[2] / T;
    const int P = in_sizes[0] / (B * C);
    float* out = (float*)d_out;

    const int CP = C * P;
    const int fast_ok = (((CP & 3) == 0) && (CP <= 1024) && (P <= 13)) ? 1 : 0;

    k_main<<<C + NMIN, TPB>>>(sims, labels, protos, pidx, mask,
                              B, C, P, T, D, fast_ok);

    // PDL launch: k_final's prologue overlaps k_main's tail; the device-side
    // cudaGridDependencySynchronize gates reads on k_main completion.
    cudaLaunchConfig_t cfg = {};
    cfg.gridDim  = dim3(148, 1, 1);
    cfg.blockDim = dim3(TPB, 1, 1);
    cfg.dynamicSmemBytes = 0;
    cfg.stream = 0;
    cudaLaunchAttribute attrs[1];
    attrs[0].id = cudaLaunchAttributeProgrammaticStreamSerialization;
    attrs[0].val.programmaticStreamSerializationAllowed = 1;
    cfg.attrs = attrs;
    cfg.numAttrs = 1;
    cudaError_t e = cudaLaunchKernelEx(&cfg, k_final, out, C, D);
    if (e != cudaSuccess) {
        // fallback: plain launch (still correct, just un-overlapped)
        k_final<<<148, TPB>>>(out, C, D);
    }
}